// round 10
// baseline (speedup 1.0000x reference)
#include <cuda_runtime.h>
#include <cuda_bf16.h>

// CenterLoss: loss = (1/(B*C)) * sum_i ||x_i - centers[labels_i]||^2
// B=4096, C=20000, D=128. Gather + reduce, single launch.
//
// Barrier-free variant: NO shared memory, NO __syncthreads, no block-level
// reduce. Each of the 4096 warps (512 blocks x 256 threads, one row per
// warp) reduces its row with shuffles and issues ONE relaxed u64 atomicAdd
// carrying a ticket (bits [63:50], counts warps) + 16.34 fixed-point
// partial (bits [49:0]). Integer adds are associative -> bit-exact
// deterministic across graph replays. The warp that draws the final ticket
// (old>>50 == 4095) holds the grand total in-register, writes the output,
// and resets the accumulator with a plain store (sole accessor; next replay
// ordered by the kernel boundary).
//
// Same-address u64 RMWs serialize at the LTS at ~0.854 cy/op (ATOMG==REDG
// under contention); 4096 ops arrive staggered over the natural CTA drain.

#define CL_BATCH 4096
#define CL_FEAT 128
#define CL_NCLASSES 20000
#define CL_WARPS 8
#define CL_THREADS (CL_WARPS * 32)                 // 256
#define CL_ROWS_PER_BLOCK CL_WARPS                 // one row per warp
#define CL_NBLOCKS (CL_BATCH / CL_ROWS_PER_BLOCK)  // 512
#define CL_NWARPS_TOTAL (CL_BATCH)                 // 4096 tickets

#define CL_TICKET_SHIFT 50
#define CL_SUM_MASK ((1ULL << CL_TICKET_SHIFT) - 1ULL)
#define CL_FIXED_SCALE 65536.0f  // 2^16 fractional bits

__device__ unsigned long long cl_g_acc = 0ULL;

__global__ void __launch_bounds__(CL_THREADS) cl_fused_kernel(
    const float* __restrict__ x,
    const int* __restrict__ labels,
    const float* __restrict__ centers,
    float* __restrict__ out)
{
    const int warp = threadIdx.x >> 5;
    const int lane = threadIdx.x & 31;
    const int row = blockIdx.x * CL_ROWS_PER_BLOCK + warp;

    // Head of the dependent chain: issue ASAP (broadcast load, 1 sector).
    const int lab = __ldg(&labels[row]);

    const float4* __restrict__ xr = reinterpret_cast<const float4*>(x + (size_t)row * CL_FEAT);
    float4 xv = xr[lane];  // independent of label, overlaps its latency

    const float4* __restrict__ cr = reinterpret_cast<const float4*>(centers + (size_t)lab * CL_FEAT);
    float4 cv = cr[lane];  // one dependent trip after label

    float dx = xv.x - cv.x;
    float dy = xv.y - cv.y;
    float dz = xv.z - cv.z;
    float dw = xv.w - cv.w;
    float s = dx * dx + dy * dy + dz * dz + dw * dw;

    // warp reduction
    #pragma unroll
    for (int o = 16; o > 0; o >>= 1)
        s += __shfl_xor_sync(0xffffffffu, s, o);

    if (lane == 0) {
        // Warp partial ~ 140 avg -> fixed ~ 9e6; 4096 warps total ~ 3.9e10 << 2^50.
        unsigned long long pkt =
            (1ULL << CL_TICKET_SHIFT) | __float2ull_rn(s * CL_FIXED_SCALE);

        unsigned long long old = atomicAdd(&cl_g_acc, pkt);

        if ((old >> CL_TICKET_SHIFT) == (unsigned long long)(CL_NWARPS_TOTAL - 1)) {
            unsigned long long total = (old + pkt) & CL_SUM_MASK;
            const float inv = 1.0f / ((float)CL_BATCH * (float)CL_NCLASSES);
            *out = (float)total * (1.0f / CL_FIXED_SCALE) * inv;
            // Sole accessor at this point; plain store resets for replay.
            cl_g_acc = 0ULL;
        }
    }
}

extern "C" void kernel_launch(void* const* d_in, const int* in_sizes, int n_in,
                              void* d_out, int out_size)
{
    const float* x       = (const float*)d_in[0];
    const int*   labels  = (const int*)d_in[1];
    const float* centers = (const float*)d_in[2];
    float* out = (float*)d_out;

    cl_fused_kernel<<<CL_NBLOCKS, CL_THREADS>>>(x, labels, centers, out);
}

// round 11
// speedup vs baseline: 1.2651x; 1.2651x over previous
#include <cuda_runtime.h>
#include <cuda_bf16.h>

// CenterLoss: loss = (1/(B*C)) * sum_i ||x_i - centers[labels_i]||^2
// B=4096, C=20000, D=128. Gather + reduce, single launch.
//
// CONVERGED CONFIGURATION (best of 10 measured variants, 6.62us wall):
// 1024 blocks x 128 threads (4 warps), one row per warp -> 4096 warps in a
// single balanced wave. Block-level pre-reduction (shared + shuffle tree),
// then ONE relaxed u64 atomicAdd per block carrying a ticket (bits [63:50])
// + 16.34 fixed-point partial (bits [49:0]). Integer adds are associative
// -> bit-exact deterministic across graph replays. The block drawing the
// last ticket holds the grand total in-register, writes the output, and
// resets the accumulator with a plain store (sole accessor; next replay is
// ordered by the kernel boundary).
//
// Measured dead ends (do not revisit): __threadfence (CCTL.IVALL L1 flush,
// +3us tail); acq_rel ticket + partials re-read (+2us); <=128 CTAs (warp
// starvation / rollout imbalance, +0.3..0.8us); per-warp atomics (4096
// same-address RMWs serialize on the last ticket's critical path, +2us).

#define CL_BATCH 4096
#define CL_FEAT 128
#define CL_NCLASSES 20000
#define CL_WARPS 4
#define CL_THREADS (CL_WARPS * 32)                 // 128
#define CL_ROWS_PER_BLOCK CL_WARPS                 // one row per warp
#define CL_NBLOCKS (CL_BATCH / CL_ROWS_PER_BLOCK)  // 1024

#define CL_TICKET_SHIFT 50
#define CL_SUM_MASK ((1ULL << CL_TICKET_SHIFT) - 1ULL)
#define CL_FIXED_SCALE 65536.0f  // 2^16 fractional bits

__device__ unsigned long long cl_g_acc = 0ULL;

__global__ void __launch_bounds__(CL_THREADS) cl_fused_kernel(
    const float* __restrict__ x,
    const int* __restrict__ labels,
    const float* __restrict__ centers,
    float* __restrict__ out)
{
    const int warp = threadIdx.x >> 5;
    const int lane = threadIdx.x & 31;
    const int row = blockIdx.x * CL_ROWS_PER_BLOCK + warp;

    // Head of the dependent chain: issue ASAP (broadcast load, 1 sector).
    const int lab = __ldg(&labels[row]);

    const float4* __restrict__ xr = reinterpret_cast<const float4*>(x + (size_t)row * CL_FEAT);
    float4 xv = xr[lane];  // independent of label, overlaps its latency

    const float4* __restrict__ cr = reinterpret_cast<const float4*>(centers + (size_t)lab * CL_FEAT);
    float4 cv = cr[lane];  // one dependent trip after label

    float dx = xv.x - cv.x;
    float dy = xv.y - cv.y;
    float dz = xv.z - cv.z;
    float dw = xv.w - cv.w;
    float s = dx * dx + dy * dy + dz * dz + dw * dw;

    // warp reduction
    #pragma unroll
    for (int o = 16; o > 0; o >>= 1)
        s += __shfl_xor_sync(0xffffffffu, s, o);

    __shared__ float sm[CL_WARPS];
    if (lane == 0) sm[warp] = s;
    __syncthreads();

    if (warp == 0) {
        // Shuffle-tree reduce of the 4 per-warp sums (lanes 0..3).
        float t = (lane < CL_WARPS) ? sm[lane] : 0.0f;
        #pragma unroll
        for (int o = 2; o > 0; o >>= 1)
            t += __shfl_xor_sync(0xffffffffu, t, o);

        if (lane == 0) {
            // Block partial ~ 570 -> fixed ~ 3.7e7; 1024 blocks ~ 3.9e10 << 2^50.
            unsigned long long pkt =
                (1ULL << CL_TICKET_SHIFT) | __float2ull_rn(t * CL_FIXED_SCALE);

            unsigned long long old = atomicAdd(&cl_g_acc, pkt);

            if ((old >> CL_TICKET_SHIFT) == (unsigned long long)(CL_NBLOCKS - 1)) {
                unsigned long long total = (old + pkt) & CL_SUM_MASK;
                const float inv = 1.0f / ((float)CL_BATCH * (float)CL_NCLASSES);
                *out = (float)total * (1.0f / CL_FIXED_SCALE) * inv;
                // Sole accessor at this point; plain store resets for replay.
                cl_g_acc = 0ULL;
            }
        }
    }
}

extern "C" void kernel_launch(void* const* d_in, const int* in_sizes, int n_in,
                              void* d_out, int out_size)
{
    const float* x       = (const float*)d_in[0];
    const int*   labels  = (const int*)d_in[1];
    const float* centers = (const float*)d_in[2];
    float* out = (float*)d_out;

    cl_fused_kernel<<<CL_NBLOCKS, CL_THREADS>>>(x, labels, centers, out);
}

// round 12
// speedup vs baseline: 1.2710x; 1.0047x over previous
#include <cuda_runtime.h>
#include <cuda_bf16.h>

// CenterLoss: loss = (1/(B*C)) * sum_i ||x_i - centers[labels_i]||^2
// B=4096, C=20000, D=128. Gather + reduce, single launch.
//
// FINAL CONVERGED KERNEL (lowest measured ncu kernel time, 5.31us; wall
// 6.6 +/- 0.3us which equals the measured per-replay floor + noise band).
//
// Structure: 512 blocks x 256 threads (8 warps), one row per warp.
//  - label load heads the dependent chain; x row load overlaps it;
//    center gather follows one memory trip later. All float4-vectorized.
//  - warp shuffle reduce -> 8 partials in shared -> lane<8 shuffle tree.
//  - ONE relaxed u64 atomicAdd per block: ticket in bits [63:50],
//    16.34 fixed-point partial in bits [49:0]. Integer adds are associative
//    -> bit-exact deterministic across graph replays.
//  - Block drawing the last ticket holds the grand total in-register,
//    writes the scaled output, and resets the accumulator with a plain
//    store (sole accessor; next replay ordered by the kernel boundary).
//
// Measured dead ends (11 rounds; do not revisit):
//  - __threadfence: gpu-scope => CCTL.IVALL L1 flush per block (+3us).
//  - acq_rel ticket + partials-array re-read: +2us.
//  - <=128 CTAs (any thread count): rollout imbalance, +0.3..0.8us.
//  - per-warp atomics (4096 same-address RMWs): last ticket waits behind
//    the serialized LTS queue, +2us.
//  - separate reduce kernel: second launch costs ~3.5us GPU-side.

#define CL_BATCH 4096
#define CL_FEAT 128
#define CL_NCLASSES 20000
#define CL_WARPS 8
#define CL_THREADS (CL_WARPS * 32)                 // 256
#define CL_ROWS_PER_BLOCK CL_WARPS                 // one row per warp
#define CL_NBLOCKS (CL_BATCH / CL_ROWS_PER_BLOCK)  // 512

#define CL_TICKET_SHIFT 50
#define CL_SUM_MASK ((1ULL << CL_TICKET_SHIFT) - 1ULL)
#define CL_FIXED_SCALE 65536.0f  // 2^16 fractional bits

__device__ unsigned long long cl_g_acc = 0ULL;

__global__ void __launch_bounds__(CL_THREADS) cl_fused_kernel(
    const float* __restrict__ x,
    const int* __restrict__ labels,
    const float* __restrict__ centers,
    float* __restrict__ out)
{
    const int warp = threadIdx.x >> 5;
    const int lane = threadIdx.x & 31;
    const int row = blockIdx.x * CL_ROWS_PER_BLOCK + warp;

    // Head of the dependent chain: issue ASAP (broadcast load, 1 sector).
    const int lab = __ldg(&labels[row]);

    const float4* __restrict__ xr = reinterpret_cast<const float4*>(x + (size_t)row * CL_FEAT);
    float4 xv = xr[lane];  // independent of label, overlaps its latency

    const float4* __restrict__ cr = reinterpret_cast<const float4*>(centers + (size_t)lab * CL_FEAT);
    float4 cv = cr[lane];  // one dependent trip after label

    float dx = xv.x - cv.x;
    float dy = xv.y - cv.y;
    float dz = xv.z - cv.z;
    float dw = xv.w - cv.w;
    float s = dx * dx + dy * dy + dz * dz + dw * dw;

    // warp reduction
    #pragma unroll
    for (int o = 16; o > 0; o >>= 1)
        s += __shfl_xor_sync(0xffffffffu, s, o);

    __shared__ float sm[CL_WARPS];
    if (lane == 0) sm[warp] = s;
    __syncthreads();

    if (warp == 0) {
        // Shuffle-tree reduce of the 8 per-warp sums (lanes 0..7).
        float t = (lane < CL_WARPS) ? sm[lane] : 0.0f;
        #pragma unroll
        for (int o = 4; o > 0; o >>= 1)
            t += __shfl_xor_sync(0xffffffffu, t, o);

        if (lane == 0) {
            // Block partial ~ 1.1e3 -> fixed ~ 7.5e7; 512 blocks ~ 3.9e10 << 2^50.
            unsigned long long pkt =
                (1ULL << CL_TICKET_SHIFT) | __float2ull_rn(t * CL_FIXED_SCALE);

            unsigned long long old = atomicAdd(&cl_g_acc, pkt);

            if ((old >> CL_TICKET_SHIFT) == (unsigned long long)(CL_NBLOCKS - 1)) {
                unsigned long long total = (old + pkt) & CL_SUM_MASK;
                const float inv = 1.0f / ((float)CL_BATCH * (float)CL_NCLASSES);
                *out = (float)total * (1.0f / CL_FIXED_SCALE) * inv;
                // Sole accessor at this point; plain store resets for replay.
                cl_g_acc = 0ULL;
            }
        }
    }
}

extern "C" void kernel_launch(void* const* d_in, const int* in_sizes, int n_in,
                              void* d_out, int out_size)
{
    const float* x       = (const float*)d_in[0];
    const int*   labels  = (const int*)d_in[1];
    const float* centers = (const float*)d_in[2];
    float* out = (float*)d_out;

    cl_fused_kernel<<<CL_NBLOCKS, CL_THREADS>>>(x, labels, centers, out);
}